// round 13
// baseline (speedup 1.0000x reference)
#include <cuda_runtime.h>
#include <cuda_fp16.h>
#include <cstdint>
#include <cstddef>

// Problem constants (B=8, T=4096, C=768)
#define BSZ  8
#define TLEN 4096
#define CDIM 768
#define MROWS (BSZ * TLEN)   // 32768
#define KDIM CDIM
#define ROWS3 (3 * CDIM)     // 2304 fused k|v|sr row

#define NSEG   64
#define SEGLEN (TLEN / NSEG)          // 64
#define LANES  (BSZ * CDIM)           // 6144
#define SEGTOT (LANES * NSEG)         // 393216
#define LANES4 (LANES / 4)            // 1536 channel-quads
#define SEGTOT4 (SEGTOT / 4)          // 98304

// ---------------- scratch (__device__ globals; no allocations allowed) -----
__device__ __align__(16) __half g_kvr[MROWS * ROWS3]; // fused k|v|sr, fp16
__device__ __align__(16) __half g_a16[MROWS * CDIM];  // activation fp16 (x, then m)
__device__ __align__(16) __half g_w16[4][CDIM * CDIM];// wk,wv,wr,wo fp16
__device__ __align__(16) float g_agg [2 * SEGTOT];
__device__ __align__(16) float g_pref[2 * SEGTOT];

// ---------------- PTX helpers (sm_80-baseline only) -------------------------
__device__ __forceinline__ uint32_t smem_to_u32(const void* p) {
    uint32_t a;
    asm("{ .reg .u64 t; cvta.to.shared.u64 t, %1; cvt.u32.u64 %0, t; }"
        : "=r"(a) : "l"(p));
    return a;
}

__device__ __forceinline__ void cp_async16(uint32_t dst, const void* src) {
    asm volatile("cp.async.cg.shared.global [%0], [%1], 16;"
                 :: "r"(dst), "l"(src) : "memory");
}
#define CP_COMMIT() asm volatile("cp.async.commit_group;" ::: "memory")
template<int N>
__device__ __forceinline__ void cp_wait() {
    asm volatile("cp.async.wait_group %0;" :: "n"(N) : "memory");
}

__device__ __forceinline__ void ldsm4(uint32_t (&r)[4], uint32_t addr) {
    asm volatile("ldmatrix.sync.aligned.m8n8.x4.shared.b16 {%0,%1,%2,%3}, [%4];"
                 : "=r"(r[0]), "=r"(r[1]), "=r"(r[2]), "=r"(r[3]) : "r"(addr));
}

__device__ __forceinline__ void mma16816(float (&d)[4], const uint32_t (&a)[4],
                                         uint32_t b0, uint32_t b1) {
    asm volatile(
        "mma.sync.aligned.m16n8k16.row.col.f32.f16.f16.f32 "
        "{%0,%1,%2,%3}, {%4,%5,%6,%7}, {%8,%9}, {%0,%1,%2,%3};"
        : "+f"(d[0]), "+f"(d[1]), "+f"(d[2]), "+f"(d[3])
        : "r"(a[0]), "r"(a[1]), "r"(a[2]), "r"(a[3]), "r"(b0), "r"(b1));
}

// ---------------------------------------------------------------------------
// HMMA GEMM: unchanged since R9 (pinned at the legacy mma.sync issue floor,
// ~571 MAC/cyc/SM across all tested tile shapes/orders).
// ---------------------------------------------------------------------------
#define BKC 32
#define NCHUNK (KDIM / BKC)            // 24
#define ROW_PITCH 80
#define TILE_BYTES (128 * ROW_PITCH)   // 10240
#define OFF_A 0
#define OFF_B TILE_BYTES
#define STAGE_BYTES (2 * TILE_BYTES)   // 20480
#define NSTAGE 3
#define GEMM_SMEM (NSTAGE * STAGE_BYTES)  // 61440

template<typename OutT>
__global__ void __launch_bounds__(256, 2) gemm_hmma_kernel(
    const __half* __restrict__ Aa, const __half* __restrict__ Bw,
    OutT* __restrict__ C, int ldc, int sigStart)
{
    extern __shared__ char smem[];
    const uint32_t sb = smem_to_u32(smem);
    const int tid  = threadIdx.x;
    const int wid  = tid >> 5;
    const int lane = tid & 31;
    const int rowBase = blockIdx.y * 128;
    const int colBase = blockIdx.x * 128;

    const char* srcs[2] = {
        (const char*)(Aa + (size_t)rowBase * KDIM),
        (const char*)(Bw + (size_t)colBase * KDIM) };

    const int lr0 = tid >> 2;          // 0..63
    const int ls  = (tid & 3) * 16;
    auto load_chunk = [&](int c, int stg) {
        const size_t colOff = (size_t)c * (BKC * 2);
        const uint32_t stgb = sb + (uint32_t)stg * STAGE_BYTES;
        #pragma unroll
        for (int t = 0; t < 2; t++) {
            const char* srcb = srcs[t] + colOff;
            const uint32_t dstb = stgb + (uint32_t)t * TILE_BYTES;
            #pragma unroll
            for (int i = 0; i < 2; i++) {
                const int r = lr0 + i * 64;
                cp_async16(dstb + (uint32_t)(r * ROW_PITCH) + ls,
                           srcb + (size_t)r * (KDIM * 2) + ls);
            }
        }
    };

    const int warpM = (wid >> 2) * 64;
    const int warpN = (wid & 3) * 32;
    const uint32_t aRow  = (uint32_t)(warpM + (lane & 15));
    const uint32_t aSegL = (uint32_t)(lane >> 4);
    const uint32_t bRow  = (uint32_t)(warpN + (lane & 7) + ((lane >> 4) & 1) * 8);
    const uint32_t bSegL = (uint32_t)((lane >> 3) & 1);

    float acc[4][4][4] = {};

    auto compute = [&](int stg) {
        const uint32_t base = sb + (uint32_t)stg * STAGE_BYTES;
        #pragma unroll
        for (int ks = 0; ks < 2; ks++) {
            uint32_t bw[2][4];
            #pragma unroll
            for (int g = 0; g < 2; g++) {
                const uint32_t bd = base + OFF_B
                                  + (bRow + g * 16) * ROW_PITCH
                                  + (ks * 2 + bSegL) * 16;
                ldsm4(bw[g], bd);
            }
            #pragma unroll
            for (int mf = 0; mf < 4; mf++) {
                uint32_t af[4];
                const uint32_t ad = base + OFF_A
                                  + (aRow + mf * 16) * ROW_PITCH
                                  + (ks * 2 + aSegL) * 16;
                ldsm4(af, ad);
                #pragma unroll
                for (int nf = 0; nf < 4; nf++)
                    mma16816(acc[mf][nf], af,
                             bw[nf >> 1][(nf & 1) * 2], bw[nf >> 1][(nf & 1) * 2 + 1]);
            }
        }
    };

    load_chunk(0, 0); CP_COMMIT();
    load_chunk(1, 1); CP_COMMIT();

    for (int c = 0; c < NCHUNK; c++) {
        cp_wait<1>();
        __syncthreads();
        if (c + 2 < NCHUNK) load_chunk(c + 2, (c + 2) % NSTAGE);
        CP_COMMIT();
        compute(c % NSTAGE);
    }

    #pragma unroll
    for (int mf = 0; mf < 4; mf++) {
        const int r0 = rowBase + warpM + mf * 16 + (lane >> 2);
        #pragma unroll
        for (int nf = 0; nf < 4; nf++) {
            const int cb = colBase + warpN + nf * 8 + (lane & 3) * 2;
            float2 lo, hi;
            lo.x = acc[mf][nf][0]; lo.y = acc[mf][nf][1];
            hi.x = acc[mf][nf][2]; hi.y = acc[mf][nf][3];
            if (cb >= sigStart) {
                lo.x = 1.0f / (1.0f + __expf(-lo.x));
                lo.y = 1.0f / (1.0f + __expf(-lo.y));
                hi.x = 1.0f / (1.0f + __expf(-hi.x));
                hi.y = 1.0f / (1.0f + __expf(-hi.y));
            }
            if constexpr (sizeof(OutT) == 2) {
                __half* Ch = (__half*)C;
                *(__half2*)(Ch + (size_t)r0 * ldc + cb) =
                    __floats2half2_rn(lo.x, lo.y);
                *(__half2*)(Ch + (size_t)(r0 + 8) * ldc + cb) =
                    __floats2half2_rn(hi.x, hi.y);
            } else {
                float* Cf = (float*)C;
                *(float2*)(Cf + (size_t)r0 * ldc + cb)       = lo;
                *(float2*)(Cf + (size_t)(r0 + 8) * ldc + cb) = hi;
            }
        }
    }
}

// ---------------------------------------------------------------------------
// Fused convert: x AND all 4 weights -> fp16, in one launch
// ---------------------------------------------------------------------------
__global__ void conv_all_kernel(
    const float* __restrict__ x,
    const float* __restrict__ w0, const float* __restrict__ w1,
    const float* __restrict__ w2, const float* __restrict__ w3,
    __half* __restrict__ a16, __half* __restrict__ w16,
    int nx4, int nw4)
{
    int i = blockIdx.x * blockDim.x + threadIdx.x;
    const float* src;
    __half* dst;
    int idx;
    if (i < nx4) {
        src = x; dst = a16; idx = i;
    } else {
        int j = i - nx4;
        if (j >= 4 * nw4) return;
        const int m = j / nw4;
        idx = j % nw4;
        src = (m == 0) ? w0 : (m == 1) ? w1 : (m == 2) ? w2 : w3;
        dst = w16 + (size_t)m * (CDIM * CDIM);
    }
    float4 v = ((const float4*)src)[idx];
    __half h[4];
    h[0] = __float2half(v.x); h[1] = __float2half(v.y);
    h[2] = __float2half(v.z); h[3] = __float2half(v.w);
    ((uint2*)dst)[idx] = *(uint2*)h;
}

// ---------------------------------------------------------------------------
// WKV parallel scan (unnormalized, 1 exp/step), 4-channel threads (uint2
// loads = 2x half2). kvr layout (b,t,c): k = [.. + c], v = +768, sr = +1536.
// ---------------------------------------------------------------------------
#define WKV_U1 8   // phase-1 prefetch depth
#define WKV_U3 4   // phase-3 prefetch depth (r buffer adds pressure)

__global__ void __launch_bounds__(256) wkv_phase1(
    const __half* __restrict__ kvr,
    const float* __restrict__ sd, float* __restrict__ agg)
{
    const int gid   = blockIdx.x * blockDim.x + threadIdx.x;   // 0..SEGTOT4-1
    const int lane4 = gid % LANES4;
    const int seg   = gid / LANES4;
    const int b  = lane4 / (CDIM / 4);
    const int c0 = (lane4 % (CDIM / 4)) * 4;

    float ew[4], A[4] = {}, Bs[4] = {};
    #pragma unroll
    for (int j = 0; j < 4; j++)
        ew[j] = __expf(sd[c0 + j] * (1.0f / (float)TLEN));

    const __half* kp = kvr + ((size_t)b * TLEN + (size_t)seg * SEGLEN) * ROWS3 + c0;

    auto loadg = [&](size_t base, uint2 (&kb)[WKV_U1], uint2 (&vb)[WKV_U1]) {
        #pragma unroll
        for (int i = 0; i < WKV_U1; i++) {
            kb[i] = *(const uint2*)(kp + base + (size_t)i * ROWS3);
            vb[i] = *(const uint2*)(kp + base + (size_t)i * ROWS3 + CDIM);
        }
    };
    auto step = [&](const uint2 (&kb)[WKV_U1], const uint2 (&vb)[WKV_U1]) {
        #pragma unroll
        for (int i = 0; i < WKV_U1; i++) {
            const float2 k0 = __half22float2(*(const __half2*)&kb[i].x);
            const float2 k1 = __half22float2(*(const __half2*)&kb[i].y);
            const float2 v0 = __half22float2(*(const __half2*)&vb[i].x);
            const float2 v1 = __half22float2(*(const __half2*)&vb[i].y);
            const float e0 = __expf(k0.x), e1 = __expf(k0.y);
            const float e2 = __expf(k1.x), e3 = __expf(k1.y);
            A[0] = fmaf(ew[0], A[0], e0 * v0.x);  Bs[0] = fmaf(ew[0], Bs[0], e0);
            A[1] = fmaf(ew[1], A[1], e1 * v0.y);  Bs[1] = fmaf(ew[1], Bs[1], e1);
            A[2] = fmaf(ew[2], A[2], e2 * v1.x);  Bs[2] = fmaf(ew[2], Bs[2], e2);
            A[3] = fmaf(ew[3], A[3], e3 * v1.y);  Bs[3] = fmaf(ew[3], Bs[3], e3);
        }
    };

    uint2 k0b[WKV_U1], v0b[WKV_U1], k1b[WKV_U1], v1b[WKV_U1];
    loadg(0, k0b, v0b);
    constexpr int NG = SEGLEN / WKV_U1;   // 8
    for (int g = 0; g < NG; g += 2) {
        loadg((size_t)(g + 1) * WKV_U1 * ROWS3, k1b, v1b);
        step(k0b, v0b);
        if (g + 2 < NG) loadg((size_t)(g + 2) * WKV_U1 * ROWS3, k0b, v0b);
        step(k1b, v1b);
    }

    const int idx = seg * LANES + b * CDIM + c0;   // mult of 4 -> 16B aligned
    *(float4*)&agg[0 * SEGTOT + idx] = make_float4(A[0], A[1], A[2], A[3]);
    *(float4*)&agg[1 * SEGTOT + idx] = make_float4(Bs[0], Bs[1], Bs[2], Bs[3]);
}

__global__ void __launch_bounds__(256) wkv_phase2(
    const float* __restrict__ agg, const float* __restrict__ sd,
    float* __restrict__ pref)
{
    const int lane = blockIdx.x * blockDim.x + threadIdx.x;
    const int c = lane % CDIM;
    const float ewseg = __expf(sd[c] * ((float)SEGLEN / (float)TLEN));

    float A = 0.0f, Bs = 0.0f;
    #pragma unroll 8
    for (int s = 0; s < NSEG; s++) {
        const int idx = s * LANES + lane;
        pref[0 * SEGTOT + idx] = A;
        pref[1 * SEGTOT + idx] = Bs;
        A  = fmaf(ewseg, A,  agg[0 * SEGTOT + idx]);
        Bs = fmaf(ewseg, Bs, agg[1 * SEGTOT + idx]);
    }
}

// Phase 3: replay segments; emit m = sigmoid(r)*y as 2x half2 (uint2 store)
__global__ void __launch_bounds__(256) wkv_phase3(
    const __half* __restrict__ kvr,
    const float* __restrict__ sd, const float* __restrict__ sf,
    const float* __restrict__ pref,
    __half* __restrict__ mh)
{
    const int gid   = blockIdx.x * blockDim.x + threadIdx.x;   // 0..SEGTOT4-1
    const int lane4 = gid % LANES4;
    const int seg   = gid / LANES4;
    const int b  = lane4 / (CDIM / 4);
    const int c0 = (lane4 % (CDIM / 4)) * 4;

    float ew[4], eu[4];
    #pragma unroll
    for (int j = 0; j < 4; j++) {
        ew[j] = __expf(sd[c0 + j] * (1.0f / (float)TLEN));
        eu[j] = __expf(sf[c0 + j] * (1.0f / (float)TLEN));
    }

    const size_t trow = (size_t)b * TLEN + (size_t)seg * SEGLEN;
    const __half* kp = kvr + trow * ROWS3 + c0;
    __half* hp = mh + trow * CDIM + c0;

    const int pidx = seg * LANES + b * CDIM + c0;
    const float4 Ap = *(const float4*)&pref[0 * SEGTOT + pidx];
    const float4 Bp = *(const float4*)&pref[1 * SEGTOT + pidx];
    float A[4]  = {Ap.x, Ap.y, Ap.z, Ap.w};
    float Bs[4] = {Bp.x, Bp.y, Bp.z, Bp.w};

    auto loadg = [&](size_t base, uint2 (&kb)[WKV_U3], uint2 (&vb)[WKV_U3],
                     uint2 (&rb)[WKV_U3]) {
        #pragma unroll
        for (int i = 0; i < WKV_U3; i++) {
            kb[i] = *(const uint2*)(kp + base + (size_t)i * ROWS3);
            vb[i] = *(const uint2*)(kp + base + (size_t)i * ROWS3 + CDIM);
            rb[i] = *(const uint2*)(kp + base + (size_t)i * ROWS3 + 2 * CDIM);
        }
    };
    auto emit = [&](const uint2 (&kb)[WKV_U3], const uint2 (&vb)[WKV_U3],
                    const uint2 (&rb)[WKV_U3], size_t tofs) {
        #pragma unroll
        for (int i = 0; i < WKV_U3; i++) {
            const float2 k0 = __half22float2(*(const __half2*)&kb[i].x);
            const float2 k1 = __half22float2(*(const __half2*)&kb[i].y);
            const float2 v0 = __half22float2(*(const __half2*)&vb[i].x);
            const float2 v1 = __half22float2(*(const __half2*)&vb[i].y);
            const float2 r0 = __half22float2(*(const __half2*)&rb[i].x);
            const float2 r1 = __half22float2(*(const __half2*)&rb[i].y);
            const float e0 = __expf(k0.x), e1 = __expf(k0.y);
            const float e2 = __expf(k1.x), e3 = __expf(k1.y);
            const float q0 = eu[0] * e0, q1 = eu[1] * e1;
            const float q2 = eu[2] * e2, q3 = eu[3] * e3;
            const float y0 = __fdividef(fmaf(q0, v0.x, A[0]), Bs[0] + q0);
            const float y1 = __fdividef(fmaf(q1, v0.y, A[1]), Bs[1] + q1);
            const float y2 = __fdividef(fmaf(q2, v1.x, A[2]), Bs[2] + q2);
            const float y3 = __fdividef(fmaf(q3, v1.y, A[3]), Bs[3] + q3);
            uint2 o;
            *(__half2*)&o.x = __floats2half2_rn(y0 * r0.x, y1 * r0.y);
            *(__half2*)&o.y = __floats2half2_rn(y2 * r1.x, y3 * r1.y);
            *(uint2*)(hp + (tofs + i) * CDIM) = o;
            A[0] = fmaf(ew[0], A[0], e0 * v0.x);  Bs[0] = fmaf(ew[0], Bs[0], e0);
            A[1] = fmaf(ew[1], A[1], e1 * v0.y);  Bs[1] = fmaf(ew[1], Bs[1], e1);
            A[2] = fmaf(ew[2], A[2], e2 * v1.x);  Bs[2] = fmaf(ew[2], Bs[2], e2);
            A[3] = fmaf(ew[3], A[3], e3 * v1.y);  Bs[3] = fmaf(ew[3], Bs[3], e3);
        }
    };

    uint2 k0b[WKV_U3], v0b[WKV_U3], r0b[WKV_U3];
    uint2 k1b[WKV_U3], v1b[WKV_U3], r1b[WKV_U3];
    loadg(0, k0b, v0b, r0b);
    constexpr int NG = SEGLEN / WKV_U3;   // 16
    for (int g = 0; g < NG; g += 2) {
        loadg((size_t)(g + 1) * WKV_U3 * ROWS3, k1b, v1b, r1b);
        emit(k0b, v0b, r0b, (size_t)g * WKV_U3);
        if (g + 2 < NG) loadg((size_t)(g + 2) * WKV_U3 * ROWS3, k0b, v0b, r0b);
        emit(k1b, v1b, r1b, (size_t)(g + 1) * WKV_U3);
    }
}

// ---------------------------------------------------------------------------
// Launch
// ---------------------------------------------------------------------------
extern "C" void kernel_launch(void* const* d_in, const int* in_sizes, int n_in,
                              void* d_out, int out_size)
{
    const float* x  = (const float*)d_in[0];
    const float* wk = (const float*)d_in[1];
    const float* wv = (const float*)d_in[2];
    const float* wr = (const float*)d_in[3];
    const float* wo = (const float*)d_in[4];
    const float* sd = (const float*)d_in[5];
    const float* sf = (const float*)d_in[6];
    float* out = (float*)d_out;

    float *gagg, *gpref;
    __half *gkvr, *a16, *w16;
    cudaGetSymbolAddress((void**)&gkvr, g_kvr);
    cudaGetSymbolAddress((void**)&gagg, g_agg);
    cudaGetSymbolAddress((void**)&gpref,g_pref);
    cudaGetSymbolAddress((void**)&a16,  g_a16);
    cudaGetSymbolAddress((void**)&w16,  g_w16);

    cudaFuncSetAttribute(gemm_hmma_kernel<__half>,
                         cudaFuncAttributeMaxDynamicSharedMemorySize, GEMM_SMEM);
    cudaFuncSetAttribute(gemm_hmma_kernel<float>,
                         cudaFuncAttributeMaxDynamicSharedMemorySize, GEMM_SMEM);

    const int nx4 = MROWS * CDIM / 4;     // 6,291,456
    const int nw4 = CDIM * CDIM / 4;      // 147,456

    // Fused convert: x + 4 weights -> fp16 in one launch
    conv_all_kernel<<<(nx4 + 4 * nw4 + 255) / 256, 256>>>(
        x, wk, wv, wr, wo, a16, w16, nx4, nw4);

    // Fused k|v|sr projection (single product), fp16 out, sigmoid cols >= 1536
    {
        dim3 fgrid(ROWS3 / 128, MROWS / 128);   // (18, 256)
        gemm_hmma_kernel<__half><<<fgrid, 256, GEMM_SMEM>>>(
            a16, w16, gkvr, ROWS3, 2 * CDIM);
    }

    // WKV scan + fused gate-mul; 4-channel vectorized phases
    wkv_phase1<<<SEGTOT4 / 256, 256>>>(gkvr, sd, gagg);            // 384 CTAs
    wkv_phase2<<<LANES / 256, 256>>>(gagg, sd, gpref);
    wkv_phase3<<<SEGTOT4 / 256, 256>>>(gkvr, sd, sf, gpref, a16);  // 384 CTAs

    // Output GEMM: single product, fp32 out, N = 768
    {
        dim3 ogrid(CDIM / 128, MROWS / 128);    // (6, 256)
        gemm_hmma_kernel<float><<<ogrid, 256, GEMM_SMEM>>>(
            a16, w16 + 3 * (size_t)CDIM * CDIM, out, CDIM, 1 << 30);
    }
}

// round 14
// speedup vs baseline: 1.0101x; 1.0101x over previous
#include <cuda_runtime.h>
#include <cuda_fp16.h>
#include <cstdint>
#include <cstddef>

// Problem constants (B=8, T=4096, C=768)
#define BSZ  8
#define TLEN 4096
#define CDIM 768
#define MROWS (BSZ * TLEN)   // 32768
#define KDIM CDIM
#define ROWS3 (3 * CDIM)     // 2304 fused k|v|sr row

#define NSEG   64
#define SEGLEN (TLEN / NSEG)          // 64
#define LANES  (BSZ * CDIM)           // 6144
#define SEGTOT (LANES * NSEG)         // 393216
#define LANES2 (LANES / 2)            // 3072 channel-pairs
#define SEGTOT2 (SEGTOT / 2)          // 196608

// ---------------- scratch (__device__ globals; no allocations allowed) -----
__device__ __align__(16) __half g_kvr[MROWS * ROWS3]; // fused k|v|sr, fp16
__device__ __align__(16) __half g_a16[MROWS * CDIM];  // activation fp16 (x, then m)
__device__ __align__(16) __half g_w16[4][CDIM * CDIM];// wk,wv,wr,wo fp16
__device__ __align__(16) float g_agg [2 * SEGTOT];
__device__ __align__(16) float g_pref[2 * SEGTOT];

// ---------------- PTX helpers (sm_80-baseline only) -------------------------
__device__ __forceinline__ uint32_t smem_to_u32(const void* p) {
    uint32_t a;
    asm("{ .reg .u64 t; cvta.to.shared.u64 t, %1; cvt.u32.u64 %0, t; }"
        : "=r"(a) : "l"(p));
    return a;
}

__device__ __forceinline__ void cp_async16(uint32_t dst, const void* src) {
    asm volatile("cp.async.cg.shared.global [%0], [%1], 16;"
                 :: "r"(dst), "l"(src) : "memory");
}
#define CP_COMMIT() asm volatile("cp.async.commit_group;" ::: "memory")
template<int N>
__device__ __forceinline__ void cp_wait() {
    asm volatile("cp.async.wait_group %0;" :: "n"(N) : "memory");
}

__device__ __forceinline__ void ldsm4(uint32_t (&r)[4], uint32_t addr) {
    asm volatile("ldmatrix.sync.aligned.m8n8.x4.shared.b16 {%0,%1,%2,%3}, [%4];"
                 : "=r"(r[0]), "=r"(r[1]), "=r"(r[2]), "=r"(r[3]) : "r"(addr));
}

__device__ __forceinline__ void mma16816(float (&d)[4], const uint32_t (&a)[4],
                                         uint32_t b0, uint32_t b1) {
    asm volatile(
        "mma.sync.aligned.m16n8k16.row.col.f32.f16.f16.f32 "
        "{%0,%1,%2,%3}, {%4,%5,%6,%7}, {%8,%9}, {%0,%1,%2,%3};"
        : "+f"(d[0]), "+f"(d[1]), "+f"(d[2]), "+f"(d[3])
        : "r"(a[0]), "r"(a[1]), "r"(a[2]), "r"(a[3]), "r"(b0), "r"(b1));
}

// ---------------------------------------------------------------------------
// HMMA GEMM: unchanged since R9 (pinned at the legacy mma.sync issue floor).
// ---------------------------------------------------------------------------
#define BKC 32
#define NCHUNK (KDIM / BKC)            // 24
#define ROW_PITCH 80
#define TILE_BYTES (128 * ROW_PITCH)   // 10240
#define OFF_A 0
#define OFF_B TILE_BYTES
#define STAGE_BYTES (2 * TILE_BYTES)   // 20480
#define NSTAGE 3
#define GEMM_SMEM (NSTAGE * STAGE_BYTES)  // 61440

template<typename OutT>
__global__ void __launch_bounds__(256, 2) gemm_hmma_kernel(
    const __half* __restrict__ Aa, const __half* __restrict__ Bw,
    OutT* __restrict__ C, int ldc, int sigStart)
{
    extern __shared__ char smem[];
    const uint32_t sb = smem_to_u32(smem);
    const int tid  = threadIdx.x;
    const int wid  = tid >> 5;
    const int lane = tid & 31;
    const int rowBase = blockIdx.y * 128;
    const int colBase = blockIdx.x * 128;

    const char* srcs[2] = {
        (const char*)(Aa + (size_t)rowBase * KDIM),
        (const char*)(Bw + (size_t)colBase * KDIM) };

    const int lr0 = tid >> 2;          // 0..63
    const int ls  = (tid & 3) * 16;
    auto load_chunk = [&](int c, int stg) {
        const size_t colOff = (size_t)c * (BKC * 2);
        const uint32_t stgb = sb + (uint32_t)stg * STAGE_BYTES;
        #pragma unroll
        for (int t = 0; t < 2; t++) {
            const char* srcb = srcs[t] + colOff;
            const uint32_t dstb = stgb + (uint32_t)t * TILE_BYTES;
            #pragma unroll
            for (int i = 0; i < 2; i++) {
                const int r = lr0 + i * 64;
                cp_async16(dstb + (uint32_t)(r * ROW_PITCH) + ls,
                           srcb + (size_t)r * (KDIM * 2) + ls);
            }
        }
    };

    const int warpM = (wid >> 2) * 64;
    const int warpN = (wid & 3) * 32;
    const uint32_t aRow  = (uint32_t)(warpM + (lane & 15));
    const uint32_t aSegL = (uint32_t)(lane >> 4);
    const uint32_t bRow  = (uint32_t)(warpN + (lane & 7) + ((lane >> 4) & 1) * 8);
    const uint32_t bSegL = (uint32_t)((lane >> 3) & 1);

    float acc[4][4][4] = {};

    auto compute = [&](int stg) {
        const uint32_t base = sb + (uint32_t)stg * STAGE_BYTES;
        #pragma unroll
        for (int ks = 0; ks < 2; ks++) {
            uint32_t bw[2][4];
            #pragma unroll
            for (int g = 0; g < 2; g++) {
                const uint32_t bd = base + OFF_B
                                  + (bRow + g * 16) * ROW_PITCH
                                  + (ks * 2 + bSegL) * 16;
                ldsm4(bw[g], bd);
            }
            #pragma unroll
            for (int mf = 0; mf < 4; mf++) {
                uint32_t af[4];
                const uint32_t ad = base + OFF_A
                                  + (aRow + mf * 16) * ROW_PITCH
                                  + (ks * 2 + aSegL) * 16;
                ldsm4(af, ad);
                #pragma unroll
                for (int nf = 0; nf < 4; nf++)
                    mma16816(acc[mf][nf], af,
                             bw[nf >> 1][(nf & 1) * 2], bw[nf >> 1][(nf & 1) * 2 + 1]);
            }
        }
    };

    load_chunk(0, 0); CP_COMMIT();
    load_chunk(1, 1); CP_COMMIT();

    for (int c = 0; c < NCHUNK; c++) {
        cp_wait<1>();
        __syncthreads();
        if (c + 2 < NCHUNK) load_chunk(c + 2, (c + 2) % NSTAGE);
        CP_COMMIT();
        compute(c % NSTAGE);
    }

    #pragma unroll
    for (int mf = 0; mf < 4; mf++) {
        const int r0 = rowBase + warpM + mf * 16 + (lane >> 2);
        #pragma unroll
        for (int nf = 0; nf < 4; nf++) {
            const int cb = colBase + warpN + nf * 8 + (lane & 3) * 2;
            float2 lo, hi;
            lo.x = acc[mf][nf][0]; lo.y = acc[mf][nf][1];
            hi.x = acc[mf][nf][2]; hi.y = acc[mf][nf][3];
            if (cb >= sigStart) {
                lo.x = 1.0f / (1.0f + __expf(-lo.x));
                lo.y = 1.0f / (1.0f + __expf(-lo.y));
                hi.x = 1.0f / (1.0f + __expf(-hi.x));
                hi.y = 1.0f / (1.0f + __expf(-hi.y));
            }
            if constexpr (sizeof(OutT) == 2) {
                __half* Ch = (__half*)C;
                *(__half2*)(Ch + (size_t)r0 * ldc + cb) =
                    __floats2half2_rn(lo.x, lo.y);
                *(__half2*)(Ch + (size_t)(r0 + 8) * ldc + cb) =
                    __floats2half2_rn(hi.x, hi.y);
            } else {
                float* Cf = (float*)C;
                *(float2*)(Cf + (size_t)r0 * ldc + cb)       = lo;
                *(float2*)(Cf + (size_t)(r0 + 8) * ldc + cb) = hi;
            }
        }
    }
}

// ---------------------------------------------------------------------------
// Fused convert: x AND all 4 weights -> fp16, in one launch
// ---------------------------------------------------------------------------
__global__ void conv_all_kernel(
    const float* __restrict__ x,
    const float* __restrict__ w0, const float* __restrict__ w1,
    const float* __restrict__ w2, const float* __restrict__ w3,
    __half* __restrict__ a16, __half* __restrict__ w16,
    int nx4, int nw4)
{
    int i = blockIdx.x * blockDim.x + threadIdx.x;
    const float* src;
    __half* dst;
    int idx;
    if (i < nx4) {
        src = x; dst = a16; idx = i;
    } else {
        int j = i - nx4;
        if (j >= 4 * nw4) return;
        const int m = j / nw4;
        idx = j % nw4;
        src = (m == 0) ? w0 : (m == 1) ? w1 : (m == 2) ? w2 : w3;
        dst = w16 + (size_t)m * (CDIM * CDIM);
    }
    float4 v = ((const float4*)src)[idx];
    __half h[4];
    h[0] = __float2half(v.x); h[1] = __float2half(v.y);
    h[2] = __float2half(v.z); h[3] = __float2half(v.w);
    ((uint2*)dst)[idx] = *(uint2*)h;
}

// ---------------------------------------------------------------------------
// WKV parallel scan (unnormalized, 1 exp/step), __half2 channel-pairing
// (R12 configuration: 768 CTAs, 2 channels/thread — the measured optimum).
// kvr layout (b,t,c): k = kvr[(b*T+t)*2304 + c], v = +768, sr = +1536.
// ---------------------------------------------------------------------------
#define WKV_U 8

__device__ __forceinline__ void wkv_load3v(
    const __half* __restrict__ kp, size_t base,
    uint32_t (&kb)[WKV_U], uint32_t (&vb)[WKV_U])
{
    #pragma unroll
    for (int i = 0; i < WKV_U; i++) {
        kb[i] = *(const uint32_t*)(kp + base + (size_t)i * ROWS3);
        vb[i] = *(const uint32_t*)(kp + base + (size_t)i * ROWS3 + CDIM);
    }
}

__global__ void __launch_bounds__(256) wkv_phase1(
    const __half* __restrict__ kvr,
    const float* __restrict__ sd, float* __restrict__ agg)
{
    const int gid   = blockIdx.x * blockDim.x + threadIdx.x;   // 0..SEGTOT2-1
    const int lane2 = gid % LANES2;
    const int seg   = gid / LANES2;
    const int b  = lane2 / (CDIM / 2);
    const int c0 = (lane2 % (CDIM / 2)) * 2;

    const float ew0 = __expf(sd[c0]     * (1.0f / (float)TLEN));
    const float ew1 = __expf(sd[c0 + 1] * (1.0f / (float)TLEN));
    const __half* kp = kvr + ((size_t)b * TLEN + (size_t)seg * SEGLEN) * ROWS3 + c0;

    float A0 = 0.0f, B0 = 0.0f, A1 = 0.0f, B1 = 0.0f;
    uint32_t k0b[WKV_U], v0b[WKV_U], k1b[WKV_U], v1b[WKV_U];
    wkv_load3v(kp, 0, k0b, v0b);

    auto step8 = [&](const uint32_t (&kb)[WKV_U], const uint32_t (&vb)[WKV_U]) {
        #pragma unroll
        for (int i = 0; i < WKV_U; i++) {
            const float2 kf = __half22float2(*(const __half2*)&kb[i]);
            const float2 vf = __half22float2(*(const __half2*)&vb[i]);
            const float e0 = __expf(kf.x);
            const float e1 = __expf(kf.y);
            A0 = fmaf(ew0, A0, e0 * vf.x);  B0 = fmaf(ew0, B0, e0);
            A1 = fmaf(ew1, A1, e1 * vf.y);  B1 = fmaf(ew1, B1, e1);
        }
    };

    constexpr int NG = SEGLEN / WKV_U;   // 8
    for (int g = 0; g < NG; g += 2) {
        wkv_load3v(kp, (size_t)(g + 1) * WKV_U * ROWS3, k1b, v1b);
        step8(k0b, v0b);
        if (g + 2 < NG)
            wkv_load3v(kp, (size_t)(g + 2) * WKV_U * ROWS3, k0b, v0b);
        step8(k1b, v1b);
    }

    const int idx = seg * LANES + b * CDIM + c0;   // even -> 8B aligned
    *(float2*)&agg[0 * SEGTOT + idx] = make_float2(A0, A1);
    *(float2*)&agg[1 * SEGTOT + idx] = make_float2(B0, B1);
}

// Phase 2: warp-parallel affine scan. One warp per lane; thread t folds
// segments {2t, 2t+1} into an affine map (m, cA, cB), Kogge-Stone composes
// across the warp, shfl-up-1 yields the exclusive prefix.
__global__ void __launch_bounds__(256) wkv_phase2(
    const float* __restrict__ agg, const float* __restrict__ sd,
    float* __restrict__ pref)
{
    const int wid  = threadIdx.x >> 5;               // warp in block: 0..7
    const int t    = threadIdx.x & 31;               // thread in warp
    const int lane = blockIdx.x * 8 + wid;           // 0..LANES-1
    const int c = lane % CDIM;
    const float ewseg = __expf(sd[c] * ((float)SEGLEN / (float)TLEN));

    const int s0 = 2 * t;
    const int i0 = s0 * LANES + lane;
    const int i1 = i0 + LANES;
    const float aA0 = agg[0 * SEGTOT + i0];
    const float aB0 = agg[1 * SEGTOT + i0];
    const float aA1 = agg[0 * SEGTOT + i1];
    const float aB1 = agg[1 * SEGTOT + i1];

    // local fold of 2 segments: x -> m*x + c
    float m  = ewseg * ewseg;
    float cA = fmaf(ewseg, aA0, aA1);
    float cB = fmaf(ewseg, aB0, aB1);

    // inclusive Kogge-Stone composition over the warp
    #pragma unroll
    for (int d = 1; d < 32; d <<= 1) {
        const float pm  = __shfl_up_sync(0xFFFFFFFFu, m,  d);
        const float pcA = __shfl_up_sync(0xFFFFFFFFu, cA, d);
        const float pcB = __shfl_up_sync(0xFFFFFFFFu, cB, d);
        if (t >= d) {
            cA = fmaf(m, pcA, cA);
            cB = fmaf(m, pcB, cB);
            m *= pm;
        }
    }

    // exclusive prefix state (state before this thread's first segment)
    float exA = __shfl_up_sync(0xFFFFFFFFu, cA, 1);
    float exB = __shfl_up_sync(0xFFFFFFFFu, cB, 1);
    if (t == 0) { exA = 0.0f; exB = 0.0f; }

    pref[0 * SEGTOT + i0] = exA;
    pref[1 * SEGTOT + i0] = exB;
    pref[0 * SEGTOT + i1] = fmaf(ewseg, exA, aA0);
    pref[1 * SEGTOT + i1] = fmaf(ewseg, exB, aB0);
}

// Phase 3: replay segments; emit m = sigmoid(r)*y as __half2
__global__ void __launch_bounds__(256) wkv_phase3(
    const __half* __restrict__ kvr,
    const float* __restrict__ sd, const float* __restrict__ sf,
    const float* __restrict__ pref,
    __half* __restrict__ mh)
{
    const int gid   = blockIdx.x * blockDim.x + threadIdx.x;   // 0..SEGTOT2-1
    const int lane2 = gid % LANES2;
    const int seg   = gid / LANES2;
    const int b  = lane2 / (CDIM / 2);
    const int c0 = (lane2 % (CDIM / 2)) * 2;

    const float ew0 = __expf(sd[c0]     * (1.0f / (float)TLEN));
    const float ew1 = __expf(sd[c0 + 1] * (1.0f / (float)TLEN));
    const float eu0 = __expf(sf[c0]     * (1.0f / (float)TLEN));
    const float eu1 = __expf(sf[c0 + 1] * (1.0f / (float)TLEN));
    const size_t trow = (size_t)b * TLEN + (size_t)seg * SEGLEN;
    const __half* kp = kvr + trow * ROWS3 + c0;
    __half* hp = mh + trow * CDIM + c0;

    const int pidx = seg * LANES + b * CDIM + c0;
    const float2 Ap = *(const float2*)&pref[0 * SEGTOT + pidx];
    const float2 Bp = *(const float2*)&pref[1 * SEGTOT + pidx];
    float A0 = Ap.x, A1 = Ap.y, B0 = Bp.x, B1 = Bp.y;

    uint32_t k0b[WKV_U], v0b[WKV_U], r0b[WKV_U];
    uint32_t k1b[WKV_U], v1b[WKV_U], r1b[WKV_U];
    wkv_load3v(kp, 0, k0b, v0b);
    #pragma unroll
    for (int i = 0; i < WKV_U; i++)
        r0b[i] = *(const uint32_t*)(kp + (size_t)i * ROWS3 + 2 * CDIM);

    auto emit = [&](const uint32_t (&kb)[WKV_U], const uint32_t (&vb)[WKV_U],
                    const uint32_t (&rb)[WKV_U], size_t tofs) {
        #pragma unroll
        for (int i = 0; i < WKV_U; i++) {
            const float2 kf = __half22float2(*(const __half2*)&kb[i]);
            const float2 vf = __half22float2(*(const __half2*)&vb[i]);
            const float2 rf = __half22float2(*(const __half2*)&rb[i]);
            const float e0 = __expf(kf.x);
            const float e1 = __expf(kf.y);
            const float euk0 = eu0 * e0;
            const float euk1 = eu1 * e1;
            const float y0 = __fdividef(fmaf(euk0, vf.x, A0), B0 + euk0);
            const float y1 = __fdividef(fmaf(euk1, vf.y, A1), B1 + euk1);
            *(__half2*)(hp + (tofs + i) * CDIM) =
                __floats2half2_rn(y0 * rf.x, y1 * rf.y);
            A0 = fmaf(ew0, A0, e0 * vf.x);  B0 = fmaf(ew0, B0, e0);
            A1 = fmaf(ew1, A1, e1 * vf.y);  B1 = fmaf(ew1, B1, e1);
        }
    };

    constexpr int NG = SEGLEN / WKV_U;   // 8
    for (int g = 0; g < NG; g += 2) {
        wkv_load3v(kp, (size_t)(g + 1) * WKV_U * ROWS3, k1b, v1b);
        #pragma unroll
        for (int i = 0; i < WKV_U; i++)
            r1b[i] = *(const uint32_t*)(kp + ((size_t)(g + 1) * WKV_U + i) * ROWS3 + 2 * CDIM);
        emit(k0b, v0b, r0b, (size_t)g * WKV_U);
        if (g + 2 < NG) {
            wkv_load3v(kp, (size_t)(g + 2) * WKV_U * ROWS3, k0b, v0b);
            #pragma unroll
            for (int i = 0; i < WKV_U; i++)
                r0b[i] = *(const uint32_t*)(kp + ((size_t)(g + 2) * WKV_U + i) * ROWS3 + 2 * CDIM);
        }
        emit(k1b, v1b, r1b, (size_t)(g + 1) * WKV_U);
    }
}

// ---------------------------------------------------------------------------
// Launch
// ---------------------------------------------------------------------------
extern "C" void kernel_launch(void* const* d_in, const int* in_sizes, int n_in,
                              void* d_out, int out_size)
{
    const float* x  = (const float*)d_in[0];
    const float* wk = (const float*)d_in[1];
    const float* wv = (const float*)d_in[2];
    const float* wr = (const float*)d_in[3];
    const float* wo = (const float*)d_in[4];
    const float* sd = (const float*)d_in[5];
    const float* sf = (const float*)d_in[6];
    float* out = (float*)d_out;

    float *gagg, *gpref;
    __half *gkvr, *a16, *w16;
    cudaGetSymbolAddress((void**)&gkvr, g_kvr);
    cudaGetSymbolAddress((void**)&gagg, g_agg);
    cudaGetSymbolAddress((void**)&gpref,g_pref);
    cudaGetSymbolAddress((void**)&a16,  g_a16);
    cudaGetSymbolAddress((void**)&w16,  g_w16);

    cudaFuncSetAttribute(gemm_hmma_kernel<__half>,
                         cudaFuncAttributeMaxDynamicSharedMemorySize, GEMM_SMEM);
    cudaFuncSetAttribute(gemm_hmma_kernel<float>,
                         cudaFuncAttributeMaxDynamicSharedMemorySize, GEMM_SMEM);

    const int nx4 = MROWS * CDIM / 4;     // 6,291,456
    const int nw4 = CDIM * CDIM / 4;      // 147,456

    // Fused convert: x + 4 weights -> fp16 in one launch
    conv_all_kernel<<<(nx4 + 4 * nw4 + 255) / 256, 256>>>(
        x, wk, wv, wr, wo, a16, w16, nx4, nw4);

    // Fused k|v|sr projection (single product), fp16 out, sigmoid cols >= 1536
    {
        dim3 fgrid(ROWS3 / 128, MROWS / 128);   // (18, 256)
        gemm_hmma_kernel<__half><<<fgrid, 256, GEMM_SMEM>>>(
            a16, w16, gkvr, ROWS3, 2 * CDIM);
    }

    // WKV scan + fused gate-mul; half2 channel-paired phases (R12 config)
    wkv_phase1<<<SEGTOT2 / 256, 256>>>(gkvr, sd, gagg);            // 768 CTAs
    wkv_phase2<<<LANES / 8, 256>>>(gagg, sd, gpref);               // 768 CTAs
    wkv_phase3<<<SEGTOT2 / 256, 256>>>(gkvr, sd, sf, gpref, a16);  // 768 CTAs

    // Output GEMM: single product, fp32 out, N = 768
    {
        dim3 ogrid(CDIM / 128, MROWS / 128);    // (6, 256)
        gemm_hmma_kernel<float><<<ogrid, 256, GEMM_SMEM>>>(
            a16, w16 + 3 * (size_t)CDIM * CDIM, out, CDIM, 1 << 30);
    }
}

// round 15
// speedup vs baseline: 1.0215x; 1.0113x over previous
#include <cuda_runtime.h>
#include <cuda_fp16.h>
#include <cstdint>
#include <cstddef>

// Problem constants (B=8, T=4096, C=768)
#define BSZ  8
#define TLEN 4096
#define CDIM 768
#define MROWS (BSZ * TLEN)   // 32768
#define KDIM CDIM
#define ROWS3 (3 * CDIM)     // 2304 fused k|v|sr row

#define NSEG   64
#define SEGLEN (TLEN / NSEG)          // 64
#define LANES  (BSZ * CDIM)           // 6144
#define SEGTOT (LANES * NSEG)         // 393216
#define LANES2 (LANES / 2)            // 3072 channel-pairs
#define SEGTOT2 (SEGTOT / 2)          // 196608

// ---------------- scratch (__device__ globals; no allocations allowed) -----
__device__ __align__(16) __half g_kvr[MROWS * ROWS3]; // fused k|v|sr, fp16
__device__ __align__(16) __half g_a16[MROWS * CDIM];  // activation fp16 (x, then m)
__device__ __align__(16) __half g_w16[4][CDIM * CDIM];// wk,wv,wr,wo fp16
__device__ __align__(16) float g_agg [2 * SEGTOT];
__device__ __align__(16) float g_pref[2 * SEGTOT];

// ---------------- PTX helpers (sm_80-baseline only) -------------------------
__device__ __forceinline__ uint32_t smem_to_u32(const void* p) {
    uint32_t a;
    asm("{ .reg .u64 t; cvta.to.shared.u64 t, %1; cvt.u32.u64 %0, t; }"
        : "=r"(a) : "l"(p));
    return a;
}

__device__ __forceinline__ void cp_async16(uint32_t dst, const void* src) {
    asm volatile("cp.async.cg.shared.global [%0], [%1], 16;"
                 :: "r"(dst), "l"(src) : "memory");
}
#define CP_COMMIT() asm volatile("cp.async.commit_group;" ::: "memory")
template<int N>
__device__ __forceinline__ void cp_wait() {
    asm volatile("cp.async.wait_group %0;" :: "n"(N) : "memory");
}

__device__ __forceinline__ void ldsm4(uint32_t (&r)[4], uint32_t addr) {
    asm volatile("ldmatrix.sync.aligned.m8n8.x4.shared.b16 {%0,%1,%2,%3}, [%4];"
                 : "=r"(r[0]), "=r"(r[1]), "=r"(r[2]), "=r"(r[3]) : "r"(addr));
}

__device__ __forceinline__ void mma16816(float (&d)[4], const uint32_t (&a)[4],
                                         uint32_t b0, uint32_t b1) {
    asm volatile(
        "mma.sync.aligned.m16n8k16.row.col.f32.f16.f16.f32 "
        "{%0,%1,%2,%3}, {%4,%5,%6,%7}, {%8,%9}, {%0,%1,%2,%3};"
        : "+f"(d[0]), "+f"(d[1]), "+f"(d[2]), "+f"(d[3])
        : "r"(a[0]), "r"(a[1]), "r"(a[2]), "r"(a[3]), "r"(b0), "r"(b1));
}

// ---------------------------------------------------------------------------
// HMMA GEMM: unchanged since R9 (pinned at the legacy mma.sync issue floor).
// ---------------------------------------------------------------------------
#define BKC 32
#define NCHUNK (KDIM / BKC)            // 24
#define ROW_PITCH 80
#define TILE_BYTES (128 * ROW_PITCH)   // 10240
#define OFF_A 0
#define OFF_B TILE_BYTES
#define STAGE_BYTES (2 * TILE_BYTES)   // 20480
#define NSTAGE 3
#define GEMM_SMEM (NSTAGE * STAGE_BYTES)  // 61440

template<typename OutT>
__global__ void __launch_bounds__(256, 2) gemm_hmma_kernel(
    const __half* __restrict__ Aa, const __half* __restrict__ Bw,
    OutT* __restrict__ C, int ldc, int sigStart)
{
    extern __shared__ char smem[];
    const uint32_t sb = smem_to_u32(smem);
    const int tid  = threadIdx.x;
    const int wid  = tid >> 5;
    const int lane = tid & 31;
    const int rowBase = blockIdx.y * 128;
    const int colBase = blockIdx.x * 128;

    const char* srcs[2] = {
        (const char*)(Aa + (size_t)rowBase * KDIM),
        (const char*)(Bw + (size_t)colBase * KDIM) };

    const int lr0 = tid >> 2;          // 0..63
    const int ls  = (tid & 3) * 16;
    auto load_chunk = [&](int c, int stg) {
        const size_t colOff = (size_t)c * (BKC * 2);
        const uint32_t stgb = sb + (uint32_t)stg * STAGE_BYTES;
        #pragma unroll
        for (int t = 0; t < 2; t++) {
            const char* srcb = srcs[t] + colOff;
            const uint32_t dstb = stgb + (uint32_t)t * TILE_BYTES;
            #pragma unroll
            for (int i = 0; i < 2; i++) {
                const int r = lr0 + i * 64;
                cp_async16(dstb + (uint32_t)(r * ROW_PITCH) + ls,
                           srcb + (size_t)r * (KDIM * 2) + ls);
            }
        }
    };

    const int warpM = (wid >> 2) * 64;
    const int warpN = (wid & 3) * 32;
    const uint32_t aRow  = (uint32_t)(warpM + (lane & 15));
    const uint32_t aSegL = (uint32_t)(lane >> 4);
    const uint32_t bRow  = (uint32_t)(warpN + (lane & 7) + ((lane >> 4) & 1) * 8);
    const uint32_t bSegL = (uint32_t)((lane >> 3) & 1);

    float acc[4][4][4] = {};

    auto compute = [&](int stg) {
        const uint32_t base = sb + (uint32_t)stg * STAGE_BYTES;
        #pragma unroll
        for (int ks = 0; ks < 2; ks++) {
            uint32_t bw[2][4];
            #pragma unroll
            for (int g = 0; g < 2; g++) {
                const uint32_t bd = base + OFF_B
                                  + (bRow + g * 16) * ROW_PITCH
                                  + (ks * 2 + bSegL) * 16;
                ldsm4(bw[g], bd);
            }
            #pragma unroll
            for (int mf = 0; mf < 4; mf++) {
                uint32_t af[4];
                const uint32_t ad = base + OFF_A
                                  + (aRow + mf * 16) * ROW_PITCH
                                  + (ks * 2 + aSegL) * 16;
                ldsm4(af, ad);
                #pragma unroll
                for (int nf = 0; nf < 4; nf++)
                    mma16816(acc[mf][nf], af,
                             bw[nf >> 1][(nf & 1) * 2], bw[nf >> 1][(nf & 1) * 2 + 1]);
            }
        }
    };

    load_chunk(0, 0); CP_COMMIT();
    load_chunk(1, 1); CP_COMMIT();

    for (int c = 0; c < NCHUNK; c++) {
        cp_wait<1>();
        __syncthreads();
        if (c + 2 < NCHUNK) load_chunk(c + 2, (c + 2) % NSTAGE);
        CP_COMMIT();
        compute(c % NSTAGE);
    }

    #pragma unroll
    for (int mf = 0; mf < 4; mf++) {
        const int r0 = rowBase + warpM + mf * 16 + (lane >> 2);
        #pragma unroll
        for (int nf = 0; nf < 4; nf++) {
            const int cb = colBase + warpN + nf * 8 + (lane & 3) * 2;
            float2 lo, hi;
            lo.x = acc[mf][nf][0]; lo.y = acc[mf][nf][1];
            hi.x = acc[mf][nf][2]; hi.y = acc[mf][nf][3];
            if (cb >= sigStart) {
                lo.x = 1.0f / (1.0f + __expf(-lo.x));
                lo.y = 1.0f / (1.0f + __expf(-lo.y));
                hi.x = 1.0f / (1.0f + __expf(-hi.x));
                hi.y = 1.0f / (1.0f + __expf(-hi.y));
            }
            if constexpr (sizeof(OutT) == 2) {
                __half* Ch = (__half*)C;
                *(__half2*)(Ch + (size_t)r0 * ldc + cb) =
                    __floats2half2_rn(lo.x, lo.y);
                *(__half2*)(Ch + (size_t)(r0 + 8) * ldc + cb) =
                    __floats2half2_rn(hi.x, hi.y);
            } else {
                float* Cf = (float*)C;
                *(float2*)(Cf + (size_t)r0 * ldc + cb)       = lo;
                *(float2*)(Cf + (size_t)(r0 + 8) * ldc + cb) = hi;
            }
        }
    }
}

// ---------------------------------------------------------------------------
// Fused convert: x AND all 4 weights -> fp16, in one launch
// ---------------------------------------------------------------------------
__global__ void conv_all_kernel(
    const float* __restrict__ x,
    const float* __restrict__ w0, const float* __restrict__ w1,
    const float* __restrict__ w2, const float* __restrict__ w3,
    __half* __restrict__ a16, __half* __restrict__ w16,
    int nx4, int nw4)
{
    int i = blockIdx.x * blockDim.x + threadIdx.x;
    const float* src;
    __half* dst;
    int idx;
    if (i < nx4) {
        src = x; dst = a16; idx = i;
    } else {
        int j = i - nx4;
        if (j >= 4 * nw4) return;
        const int m = j / nw4;
        idx = j % nw4;
        src = (m == 0) ? w0 : (m == 1) ? w1 : (m == 2) ? w2 : w3;
        dst = w16 + (size_t)m * (CDIM * CDIM);
    }
    float4 v = ((const float4*)src)[idx];
    __half h[4];
    h[0] = __float2half(v.x); h[1] = __float2half(v.y);
    h[2] = __float2half(v.z); h[3] = __float2half(v.w);
    ((uint2*)dst)[idx] = *(uint2*)h;
}

// ---------------------------------------------------------------------------
// WKV parallel scan (unnormalized, 1 exp/step), __half2 channel-pairing
// (R12 configuration for phases 1/3: 768 CTAs, 2 channels/thread).
// kvr layout (b,t,c): k = kvr[(b*T+t)*2304 + c], v = +768, sr = +1536.
// ---------------------------------------------------------------------------
#define WKV_U 8

__device__ __forceinline__ void wkv_load3v(
    const __half* __restrict__ kp, size_t base,
    uint32_t (&kb)[WKV_U], uint32_t (&vb)[WKV_U])
{
    #pragma unroll
    for (int i = 0; i < WKV_U; i++) {
        kb[i] = *(const uint32_t*)(kp + base + (size_t)i * ROWS3);
        vb[i] = *(const uint32_t*)(kp + base + (size_t)i * ROWS3 + CDIM);
    }
}

__global__ void __launch_bounds__(256) wkv_phase1(
    const __half* __restrict__ kvr,
    const float* __restrict__ sd, float* __restrict__ agg)
{
    const int gid   = blockIdx.x * blockDim.x + threadIdx.x;   // 0..SEGTOT2-1
    const int lane2 = gid % LANES2;
    const int seg   = gid / LANES2;
    const int b  = lane2 / (CDIM / 2);
    const int c0 = (lane2 % (CDIM / 2)) * 2;

    const float ew0 = __expf(sd[c0]     * (1.0f / (float)TLEN));
    const float ew1 = __expf(sd[c0 + 1] * (1.0f / (float)TLEN));
    const __half* kp = kvr + ((size_t)b * TLEN + (size_t)seg * SEGLEN) * ROWS3 + c0;

    float A0 = 0.0f, B0 = 0.0f, A1 = 0.0f, B1 = 0.0f;
    uint32_t k0b[WKV_U], v0b[WKV_U], k1b[WKV_U], v1b[WKV_U];
    wkv_load3v(kp, 0, k0b, v0b);

    auto step8 = [&](const uint32_t (&kb)[WKV_U], const uint32_t (&vb)[WKV_U]) {
        #pragma unroll
        for (int i = 0; i < WKV_U; i++) {
            const float2 kf = __half22float2(*(const __half2*)&kb[i]);
            const float2 vf = __half22float2(*(const __half2*)&vb[i]);
            const float e0 = __expf(kf.x);
            const float e1 = __expf(kf.y);
            A0 = fmaf(ew0, A0, e0 * vf.x);  B0 = fmaf(ew0, B0, e0);
            A1 = fmaf(ew1, A1, e1 * vf.y);  B1 = fmaf(ew1, B1, e1);
        }
    };

    constexpr int NG = SEGLEN / WKV_U;   // 8
    for (int g = 0; g < NG; g += 2) {
        wkv_load3v(kp, (size_t)(g + 1) * WKV_U * ROWS3, k1b, v1b);
        step8(k0b, v0b);
        if (g + 2 < NG)
            wkv_load3v(kp, (size_t)(g + 2) * WKV_U * ROWS3, k0b, v0b);
        step8(k1b, v1b);
    }

    const int idx = seg * LANES + b * CDIM + c0;   // even -> 8B aligned
    *(float2*)&agg[0 * SEGTOT + idx] = make_float2(A0, A1);
    *(float2*)&agg[1 * SEGTOT + idx] = make_float2(B0, B1);
}

// Phase 2: warp-parallel affine scan with SMEM-transposed coalesced I/O.
// Block serves 8 lanes: cooperative 32B-run loads into s[64][9], warp w
// Kogge-Stone scans lane w's 64 segments, results staged back via smem.
__global__ void __launch_bounds__(256) wkv_phase2(
    const float* __restrict__ agg, const float* __restrict__ sd,
    float* __restrict__ pref)
{
    __shared__ float sA[NSEG][9], sB[NSEG][9];
    const int tid   = threadIdx.x;
    const int lane0 = blockIdx.x * 8;

    // cooperative coalesced load: thread i -> (seg = i>>3, l = i&7)
    #pragma unroll
    for (int j = 0; j < 2; j++) {
        const int idx = j * 256 + tid;
        const int s = idx >> 3, l = idx & 7;
        sA[s][l] = agg[0 * SEGTOT + s * LANES + lane0 + l];
        sB[s][l] = agg[1 * SEGTOT + s * LANES + lane0 + l];
    }
    __syncthreads();

    const int w = tid >> 5;            // warp -> lane_local
    const int t = tid & 31;
    const int c = (lane0 + w) % CDIM;
    const float ewseg = __expf(sd[c] * ((float)SEGLEN / (float)TLEN));

    const float aA0 = sA[2 * t][w],     aA1 = sA[2 * t + 1][w];
    const float aB0 = sB[2 * t][w],     aB1 = sB[2 * t + 1][w];

    // local fold of 2 segments: x -> m*x + c
    float m  = ewseg * ewseg;
    float cA = fmaf(ewseg, aA0, aA1);
    float cB = fmaf(ewseg, aB0, aB1);

    // inclusive Kogge-Stone composition over the warp (32 pairs = 64 segs)
    #pragma unroll
    for (int d = 1; d < 32; d <<= 1) {
        const float pm  = __shfl_up_sync(0xFFFFFFFFu, m,  d);
        const float pcA = __shfl_up_sync(0xFFFFFFFFu, cA, d);
        const float pcB = __shfl_up_sync(0xFFFFFFFFu, cB, d);
        if (t >= d) {
            cA = fmaf(m, pcA, cA);
            cB = fmaf(m, pcB, cB);
            m *= pm;
        }
    }

    float exA = __shfl_up_sync(0xFFFFFFFFu, cA, 1);
    float exB = __shfl_up_sync(0xFFFFFFFFu, cB, 1);
    if (t == 0) { exA = 0.0f; exB = 0.0f; }

    // stage exclusive prefixes back (column w is warp-private)
    sA[2 * t][w]     = exA;
    sA[2 * t + 1][w] = fmaf(ewseg, exA, aA0);
    sB[2 * t][w]     = exB;
    sB[2 * t + 1][w] = fmaf(ewseg, exB, aB0);
    __syncthreads();

    // cooperative coalesced store
    #pragma unroll
    for (int j = 0; j < 2; j++) {
        const int idx = j * 256 + tid;
        const int s = idx >> 3, l = idx & 7;
        pref[0 * SEGTOT + s * LANES + lane0 + l] = sA[s][l];
        pref[1 * SEGTOT + s * LANES + lane0 + l] = sB[s][l];
    }
}

// Phase 3: replay segments; emit m = sigmoid(r)*y as __half2
__global__ void __launch_bounds__(256) wkv_phase3(
    const __half* __restrict__ kvr,
    const float* __restrict__ sd, const float* __restrict__ sf,
    const float* __restrict__ pref,
    __half* __restrict__ mh)
{
    const int gid   = blockIdx.x * blockDim.x + threadIdx.x;   // 0..SEGTOT2-1
    const int lane2 = gid % LANES2;
    const int seg   = gid / LANES2;
    const int b  = lane2 / (CDIM / 2);
    const int c0 = (lane2 % (CDIM / 2)) * 2;

    const float ew0 = __expf(sd[c0]     * (1.0f / (float)TLEN));
    const float ew1 = __expf(sd[c0 + 1] * (1.0f / (float)TLEN));
    const float eu0 = __expf(sf[c0]     * (1.0f / (float)TLEN));
    const float eu1 = __expf(sf[c0 + 1] * (1.0f / (float)TLEN));
    const size_t trow = (size_t)b * TLEN + (size_t)seg * SEGLEN;
    const __half* kp = kvr + trow * ROWS3 + c0;
    __half* hp = mh + trow * CDIM + c0;

    const int pidx = seg * LANES + b * CDIM + c0;
    const float2 Ap = *(const float2*)&pref[0 * SEGTOT + pidx];
    const float2 Bp = *(const float2*)&pref[1 * SEGTOT + pidx];
    float A0 = Ap.x, A1 = Ap.y, B0 = Bp.x, B1 = Bp.y;

    uint32_t k0b[WKV_U], v0b[WKV_U], r0b[WKV_U];
    uint32_t k1b[WKV_U], v1b[WKV_U], r1b[WKV_U];
    wkv_load3v(kp, 0, k0b, v0b);
    #pragma unroll
    for (int i = 0; i < WKV_U; i++)
        r0b[i] = *(const uint32_t*)(kp + (size_t)i * ROWS3 + 2 * CDIM);

    auto emit = [&](const uint32_t (&kb)[WKV_U], const uint32_t (&vb)[WKV_U],
                    const uint32_t (&rb)[WKV_U], size_t tofs) {
        #pragma unroll
        for (int i = 0; i < WKV_U; i++) {
            const float2 kf = __half22float2(*(const __half2*)&kb[i]);
            const float2 vf = __half22float2(*(const __half2*)&vb[i]);
            const float2 rf = __half22float2(*(const __half2*)&rb[i]);
            const float e0 = __expf(kf.x);
            const float e1 = __expf(kf.y);
            const float euk0 = eu0 * e0;
            const float euk1 = eu1 * e1;
            const float y0 = __fdividef(fmaf(euk0, vf.x, A0), B0 + euk0);
            const float y1 = __fdividef(fmaf(euk1, vf.y, A1), B1 + euk1);
            *(__half2*)(hp + (tofs + i) * CDIM) =
                __floats2half2_rn(y0 * rf.x, y1 * rf.y);
            A0 = fmaf(ew0, A0, e0 * vf.x);  B0 = fmaf(ew0, B0, e0);
            A1 = fmaf(ew1, A1, e1 * vf.y);  B1 = fmaf(ew1, B1, e1);
        }
    };

    constexpr int NG = SEGLEN / WKV_U;   // 8
    for (int g = 0; g < NG; g += 2) {
        wkv_load3v(kp, (size_t)(g + 1) * WKV_U * ROWS3, k1b, v1b);
        #pragma unroll
        for (int i = 0; i < WKV_U; i++)
            r1b[i] = *(const uint32_t*)(kp + ((size_t)(g + 1) * WKV_U + i) * ROWS3 + 2 * CDIM);
        emit(k0b, v0b, r0b, (size_t)g * WKV_U);
        if (g + 2 < NG) {
            wkv_load3v(kp, (size_t)(g + 2) * WKV_U * ROWS3, k0b, v0b);
            #pragma unroll
            for (int i = 0; i < WKV_U; i++)
                r0b[i] = *(const uint32_t*)(kp + ((size_t)(g + 2) * WKV_U + i) * ROWS3 + 2 * CDIM);
        }
        emit(k1b, v1b, r1b, (size_t)(g + 1) * WKV_U);
    }
}

// ---------------------------------------------------------------------------
// Launch
// ---------------------------------------------------------------------------
extern "C" void kernel_launch(void* const* d_in, const int* in_sizes, int n_in,
                              void* d_out, int out_size)
{
    const float* x  = (const float*)d_in[0];
    const float* wk = (const float*)d_in[1];
    const float* wv = (const float*)d_in[2];
    const float* wr = (const float*)d_in[3];
    const float* wo = (const float*)d_in[4];
    const float* sd = (const float*)d_in[5];
    const float* sf = (const float*)d_in[6];
    float* out = (float*)d_out;

    float *gagg, *gpref;
    __half *gkvr, *a16, *w16;
    cudaGetSymbolAddress((void**)&gkvr, g_kvr);
    cudaGetSymbolAddress((void**)&gagg, g_agg);
    cudaGetSymbolAddress((void**)&gpref,g_pref);
    cudaGetSymbolAddress((void**)&a16,  g_a16);
    cudaGetSymbolAddress((void**)&w16,  g_w16);

    cudaFuncSetAttribute(gemm_hmma_kernel<__half>,
                         cudaFuncAttributeMaxDynamicSharedMemorySize, GEMM_SMEM);
    cudaFuncSetAttribute(gemm_hmma_kernel<float>,
                         cudaFuncAttributeMaxDynamicSharedMemorySize, GEMM_SMEM);

    const int nx4 = MROWS * CDIM / 4;     // 6,291,456
    const int nw4 = CDIM * CDIM / 4;      // 147,456

    // Fused convert: x + 4 weights -> fp16 in one launch
    conv_all_kernel<<<(nx4 + 4 * nw4 + 255) / 256, 256>>>(
        x, wk, wv, wr, wo, a16, w16, nx4, nw4);

    // Fused k|v|sr projection (single product), fp16 out, sigmoid cols >= 1536
    {
        dim3 fgrid(ROWS3 / 128, MROWS / 128);   // (18, 256)
        gemm_hmma_kernel<__half><<<fgrid, 256, GEMM_SMEM>>>(
            a16, w16, gkvr, ROWS3, 2 * CDIM);
    }

    // WKV scan + fused gate-mul
    wkv_phase1<<<SEGTOT2 / 256, 256>>>(gkvr, sd, gagg);            // 768 CTAs
    wkv_phase2<<<LANES / 8, 256>>>(gagg, sd, gpref);               // 768 CTAs
    wkv_phase3<<<SEGTOT2 / 256, 256>>>(gkvr, sd, sf, gpref, a16);  // 768 CTAs

    // Output GEMM: single product, fp32 out, N = 768
    {
        dim3 ogrid(CDIM / 128, MROWS / 128);    // (6, 256)
        gemm_hmma_kernel<float><<<ogrid, 256, GEMM_SMEM>>>(
            a16, w16 + 3 * (size_t)CDIM * CDIM, out, CDIM, 1 << 30);
    }
}